// round 12
// baseline (speedup 1.0000x reference)
#include <cuda_runtime.h>
#include <cuda_bf16.h>
#include <cstdint>

// adaptive_avg_pool2d(x[32,2048,28,28], 7) -> out[32,49,2048]
// linspace(0,28,8) = 0,4,...,28 => exact uniform 4x4 windows.
//
// R12 = R10 verbatim (best measured: bench 33.28us = kernel dur, DRAM 81%,
// 6.43 TB/s ~= 95% of the measured LTS/HBM path-independent ceiling).
// Final design:
//  - 8192 short blocks (256 thr): fine granularity -> no scheduler tail
//    (R4/R11 showed coarser blocks re-expose drain-tail idle).
//  - One channel per warp; 7xLDG.128 front batch (MLP=7) with __ldcs
//    (evict-first; all input touch-once). launch_bounds(256,6) gives the
//    42-reg budget the batch needs (tighter caps made ptxas break it: R8).
//  - Raw horizontal 4-sums -> per-warp smem stage (plain STS); warp-local
//    vertical 4-row reduce (no atomics: R3's 2x win); single *0.0625 at end.
//  - Loop-free writeout: 196 STG.64 __stcs per block, transposed layout
//    already coalesced in the channel dimension.
// Rejected by measurement: smem atomics (R1-2), single-wave grid (R4),
// cp.async (R7), reg-cap 36 (R8), 512-thread blocks (R11).

#define CCH    2048
#define HW     784
#define TILE_C 8
#define ACC_STRIDE 57    // odd stride: conflict-free transposed readout
#define STG_STRIDE 200   // per-warp stage stride

__global__ __launch_bounds__(256, 6)
void upp_pool_kernel(const float* __restrict__ x, float* __restrict__ out) {
    __shared__ float stage[8 * STG_STRIDE];     // 6400 B
    __shared__ float acc[TILE_C * ACC_STRIDE];  // 1824 B

    const int tid  = threadIdx.x;
    const int warp = tid >> 5;     // = c_local: one channel per warp
    const int lane = tid & 31;

    const float4* __restrict__ plane =
        reinterpret_cast<const float4*>(
            x + ((size_t)(blockIdx.y * CCH + blockIdx.x * TILE_C + warp)) * HW)
        + lane;

    // Phase 1: front-batch ALL 7 LDG.128 (MLP=7), streaming (evict-first).
    const float4 v0 = __ldcs(plane +   0);
    const float4 v1 = __ldcs(plane +  32);
    const float4 v2 = __ldcs(plane +  64);
    const float4 v3 = __ldcs(plane +  96);
    const float4 v4 = __ldcs(plane + 128);
    const float4 v5 = __ldcs(plane + 160);
    float4 v6 = make_float4(0.f, 0.f, 0.f, 0.f);
    if (lane < 4) v6 = __ldcs(plane + 192);

    // Raw horizontal 4-sums -> per-warp stage (scale deferred to phase 2)
    const int wbase = warp * STG_STRIDE + lane;
    stage[wbase +   0] = (v0.x + v0.y) + (v0.z + v0.w);
    stage[wbase +  32] = (v1.x + v1.y) + (v1.z + v1.w);
    stage[wbase +  64] = (v2.x + v2.y) + (v2.z + v2.w);
    stage[wbase +  96] = (v3.x + v3.y) + (v3.z + v3.w);
    stage[wbase + 128] = (v4.x + v4.y) + (v4.z + v4.w);
    stage[wbase + 160] = (v5.x + v5.y) + (v5.z + v5.w);
    if (lane < 4)
        stage[wbase + 192] = (v6.x + v6.y) + (v6.z + v6.w);
    __syncwarp();

    // Phase 2: vertical reduce over 4 rows per bin; single scale at the end.
    {
        const int o0 = warp * STG_STRIDE + 28 * (lane / 7) + (lane % 7);
        acc[warp * ACC_STRIDE + lane] =
            ((stage[o0] + stage[o0 + 7]) +
             (stage[o0 + 14] + stage[o0 + 21])) * 0.0625f;
    }
    if (lane < 17) {
        const int b1 = lane + 32;
        const int o1 = warp * STG_STRIDE + 28 * (b1 / 7) + (b1 % 7);
        acc[warp * ACC_STRIDE + b1] =
            ((stage[o1] + stage[o1 + 7]) +
             (stage[o1 + 14] + stage[o1 + 21])) * 0.0625f;
    }
    __syncthreads();

    // Writeout, loop-free: 49 p-rows x 8 channels = 196 STG.64.
    // Thread t (<196): p = t/4, channel pair c = 2*(t&3).
    if (tid < 196) {
        const int p = tid >> 2;
        const int c = (tid & 3) * 2;
        const float2 w = make_float2(acc[c * ACC_STRIDE + p],
                                     acc[(c + 1) * ACC_STRIDE + p]);
        float2* __restrict__ ob = reinterpret_cast<float2*>(
            out + (size_t)blockIdx.y * 49 * CCH + blockIdx.x * TILE_C
                + p * CCH + c);
        __stcs(ob, w);
    }
}

extern "C" void kernel_launch(void* const* d_in, const int* in_sizes, int n_in,
                              void* d_out, int out_size) {
    const float* x = (const float*)d_in[0];
    float* out = (float*)d_out;
    dim3 grid(CCH / TILE_C, 32);   // (256, 32) = 8192 short blocks
    upp_pool_kernel<<<grid, 256>>>(x, out);
}

// round 13
// speedup vs baseline: 1.0082x; 1.0082x over previous
#include <cuda_runtime.h>
#include <cuda_bf16.h>
#include <cstdint>

// adaptive_avg_pool2d(x[32,2048,28,28], 7) -> out[32,49,2048]
// linspace(0,28,8) = 0,4,...,28 => exact uniform 4x4 windows.
//
// R13 = R10 with one surgical change: writeout stores are PLAIN (default
// evict policy) instead of __stcs. Each block writes only a 32B sector of
// each 128B output line (TILE_C=8); the line fills only when 4 adjacent
// blocks' writes merge in L2. evict-first on those partial writes risks
// early eviction -> partial-sector DRAM writeback -> HBM read-modify-write
// (~12.8MB hidden RMW reads). Reads keep __ldcs (touch-once, full lines:
// evict-first is correct there).
//
// Frozen core (best measured, kernel 33.2us, ~6.44 TB/s ~= 95% of the
// measured LTS/HBM achievable ceiling):
//  - 8192 short 256-thread blocks (fine granularity -> no scheduler tail)
//  - one channel per warp; 7xLDG.128 front batch (MLP=7) with __ldcs
//  - launch_bounds(256,6): 42-reg budget preserves the batch (regs=38)
//  - raw 4-sums -> per-warp smem stage; warp-local vertical reduce, no
//    atomics; single *0.0625 at the end
//  - loop-free writeout: 196 STG.64 per block
// Rejected by measurement: smem atomics (R1-2), single-wave grid (R4),
// cp.async (R7), reg-cap 36 (R8), 512-thread blocks (R11).

#define CCH    2048
#define HW     784
#define TILE_C 8
#define ACC_STRIDE 57    // odd stride: conflict-free transposed readout
#define STG_STRIDE 200   // per-warp stage stride

__global__ __launch_bounds__(256, 6)
void upp_pool_kernel(const float* __restrict__ x, float* __restrict__ out) {
    __shared__ float stage[8 * STG_STRIDE];     // 6400 B
    __shared__ float acc[TILE_C * ACC_STRIDE];  // 1824 B

    const int tid  = threadIdx.x;
    const int warp = tid >> 5;     // = c_local: one channel per warp
    const int lane = tid & 31;

    const float4* __restrict__ plane =
        reinterpret_cast<const float4*>(
            x + ((size_t)(blockIdx.y * CCH + blockIdx.x * TILE_C + warp)) * HW)
        + lane;

    // Phase 1: front-batch ALL 7 LDG.128 (MLP=7), streaming (evict-first).
    const float4 v0 = __ldcs(plane +   0);
    const float4 v1 = __ldcs(plane +  32);
    const float4 v2 = __ldcs(plane +  64);
    const float4 v3 = __ldcs(plane +  96);
    const float4 v4 = __ldcs(plane + 128);
    const float4 v5 = __ldcs(plane + 160);
    float4 v6 = make_float4(0.f, 0.f, 0.f, 0.f);
    if (lane < 4) v6 = __ldcs(plane + 192);

    // Raw horizontal 4-sums -> per-warp stage (scale deferred to phase 2)
    const int wbase = warp * STG_STRIDE + lane;
    stage[wbase +   0] = (v0.x + v0.y) + (v0.z + v0.w);
    stage[wbase +  32] = (v1.x + v1.y) + (v1.z + v1.w);
    stage[wbase +  64] = (v2.x + v2.y) + (v2.z + v2.w);
    stage[wbase +  96] = (v3.x + v3.y) + (v3.z + v3.w);
    stage[wbase + 128] = (v4.x + v4.y) + (v4.z + v4.w);
    stage[wbase + 160] = (v5.x + v5.y) + (v5.z + v5.w);
    if (lane < 4)
        stage[wbase + 192] = (v6.x + v6.y) + (v6.z + v6.w);
    __syncwarp();

    // Phase 2: vertical reduce over 4 rows per bin; single scale at the end.
    {
        const int o0 = warp * STG_STRIDE + 28 * (lane / 7) + (lane % 7);
        acc[warp * ACC_STRIDE + lane] =
            ((stage[o0] + stage[o0 + 7]) +
             (stage[o0 + 14] + stage[o0 + 21])) * 0.0625f;
    }
    if (lane < 17) {
        const int b1 = lane + 32;
        const int o1 = warp * STG_STRIDE + 28 * (b1 / 7) + (b1 % 7);
        acc[warp * ACC_STRIDE + b1] =
            ((stage[o1] + stage[o1 + 7]) +
             (stage[o1 + 14] + stage[o1 + 21])) * 0.0625f;
    }
    __syncthreads();

    // Writeout, loop-free: 49 p-rows x 8 channels = 196 STG.64.
    // Thread t (<196): p = t/4, channel pair c = 2*(t&3). PLAIN stores:
    // partial-line sectors must linger in L2 to merge with neighbor blocks.
    if (tid < 196) {
        const int p = tid >> 2;
        const int c = (tid & 3) * 2;
        const float2 w = make_float2(acc[c * ACC_STRIDE + p],
                                     acc[(c + 1) * ACC_STRIDE + p]);
        float2* __restrict__ ob = reinterpret_cast<float2*>(
            out + (size_t)blockIdx.y * 49 * CCH + blockIdx.x * TILE_C
                + p * CCH + c);
        *ob = w;
    }
}

extern "C" void kernel_launch(void* const* d_in, const int* in_sizes, int n_in,
                              void* d_out, int out_size) {
    const float* x = (const float*)d_in[0];
    float* out = (float*)d_out;
    dim3 grid(CCH / TILE_C, 32);   // (256, 32) = 8192 short blocks
    upp_pool_kernel<<<grid, 256>>>(x, out);
}